// round 15
// baseline (speedup 1.0000x reference)
#include <cuda_runtime.h>
#include <cuda_fp16.h>

#define N_NODES 100000
#define N_EDGES 3200000
#define R0 16
#define R1 8
#define R2 16
#define N1 32

// ---------------- scratch (device globals; no allocation allowed) ----------------
__device__ __align__(16) __half g_y1h[N_NODES * R1];  // x @ W_rel1, fp16 rows (gathered)
__device__ __align__(16) float  g_r1[N_NODES * R1];   // x @ W_root1 + b_rel1 (exact)
__device__ __align__(16) float  g_agg1[N_NODES * R1]; // layer-1 aggregate (fp32)
__device__ __align__(16) __half g_h1h[N_NODES * R1];  // layer-1 out, fp16 rows
__device__ __align__(16) float  g_agg2[N_NODES * R1]; // layer-2 aggregate (fp32)
__device__ double g_sum;

// vector reduction: one L2 op covers 16B (4 floats), no return value
__device__ __forceinline__ void red_add_v4(float* p, float a, float b, float c, float d) {
    asm volatile("red.global.add.v4.f32 [%0], {%1, %2, %3, %4};"
                 :: "l"(p), "f"(a), "f"(b), "f"(c), "f"(d)
                 : "memory");
}

// pack 8 floats -> 8 halves (16B)
__device__ __forceinline__ uint4 pack_half8(const float* v) {
    __half2 h0 = __float22half2_rn(make_float2(v[0], v[1]));
    __half2 h1 = __float22half2_rn(make_float2(v[2], v[3]));
    __half2 h2 = __float22half2_rn(make_float2(v[4], v[5]));
    __half2 h3 = __float22half2_rn(make_float2(v[6], v[7]));
    uint4 u;
    u.x = *reinterpret_cast<unsigned*>(&h0);
    u.y = *reinterpret_cast<unsigned*>(&h1);
    u.z = *reinterpret_cast<unsigned*>(&h2);
    u.w = *reinterpret_cast<unsigned*>(&h3);
    return u;
}

// unpack a 16B half8 row into 8 floats
__device__ __forceinline__ void unpack_half8(float* f, uint4 u) {
    __half2 h0 = *reinterpret_cast<__half2*>(&u.x);
    __half2 h1 = *reinterpret_cast<__half2*>(&u.y);
    __half2 h2 = *reinterpret_cast<__half2*>(&u.z);
    __half2 h3 = *reinterpret_cast<__half2*>(&u.w);
    float2 f0 = __half22float2(h0), f1 = __half22float2(h1);
    float2 f2 = __half22float2(h2), f3 = __half22float2(h3);
    f[0] = f0.x; f[1] = f0.y; f[2] = f1.x; f[3] = f1.y;
    f[4] = f2.x; f[5] = f2.y; f[6] = f3.x; f[7] = f3.y;
}

// ---------------- K1: per-node pre-transform + zero agg1 + zero sum ----------------
__global__ __launch_bounds__(128)
void k_node1(const float* __restrict__ x,
             const float* __restrict__ Wrel,
             const float* __restrict__ brel,
             const float* __restrict__ Wroot) {
    __shared__ float sWr[R0 * R1];
    __shared__ float sWo[R0 * R1];
    __shared__ float sb[R1];
    int t = threadIdx.x;
    if (t < R0 * R1) { sWr[t] = Wrel[t]; sWo[t] = Wroot[t]; }
    if (t < R1) sb[t] = brel[t];
    __syncthreads();

    int i = blockIdx.x * blockDim.x + t;
    if (i == 0) g_sum = 0.0;
    if (i >= N_NODES) return;

    float xr[R0];
    const float4* xp = reinterpret_cast<const float4*>(x + (size_t)i * R0);
#pragma unroll
    for (int q = 0; q < R0 / 4; q++) {
        float4 v = xp[q];
        xr[4 * q + 0] = v.x; xr[4 * q + 1] = v.y;
        xr[4 * q + 2] = v.z; xr[4 * q + 3] = v.w;
    }

    float y[R1], r[R1];
#pragma unroll
    for (int k = 0; k < R1; k++) { y[k] = 0.f; r[k] = sb[k]; }
#pragma unroll
    for (int j = 0; j < R0; j++) {
        float xj = xr[j];
#pragma unroll
        for (int k = 0; k < R1; k++) {
            y[k] += xj * sWr[j * R1 + k];
            r[k] += xj * sWo[j * R1 + k];
        }
    }

    reinterpret_cast<uint4*>(g_y1h)[i] = pack_half8(y);
    float4* rp = reinterpret_cast<float4*>(g_r1 + (size_t)i * R1);
    rp[0] = make_float4(r[0], r[1], r[2], r[3]);
    rp[1] = make_float4(r[4], r[5], r[6], r[7]);

    float4 z = make_float4(0.f, 0.f, 0.f, 0.f);
    float4* a1 = reinterpret_cast<float4*>(g_agg1 + (size_t)i * R1);
    a1[0] = z; a1[1] = z;
}

// ---------------- K2/K4: push pass, 2 edges/thread (at LTS wall) ----------------
template <int LAYER>
__global__ __launch_bounds__(256, 8)
void k_push(const int* __restrict__ ei) {
    int base = (blockIdx.x * blockDim.x + threadIdx.x) * 2;
    // grid exact: 6250 blocks x 256 threads x 2 edges = 3.2M

    const uint4* rows = reinterpret_cast<const uint4*>(LAYER == 1 ? g_y1h : g_h1h);
    float* agg = (LAYER == 1) ? g_agg1 : g_agg2;

    int2 s = __ldg(reinterpret_cast<const int2*>(ei + base));
    int2 d = __ldg(reinterpret_cast<const int2*>(ei + N_EDGES + base));

    // both gathers in flight before any use
    uint4 r0 = __ldg(rows + s.x);
    uint4 r1 = __ldg(rows + s.y);

    {
        float f[8]; unpack_half8(f, r0);
        float* q = agg + (size_t)d.x * R1;
        red_add_v4(q,     f[0], f[1], f[2], f[3]);
        red_add_v4(q + 4, f[4], f[5], f[6], f[7]);
    }
    {
        float f[8]; unpack_half8(f, r1);
        float* q = agg + (size_t)d.y * R1;
        red_add_v4(q,     f[0], f[1], f[2], f[3]);
        red_add_v4(q + 4, f[4], f[5], f[6], f[7]);
    }
}

// ---------------- K3: h1 = relu(agg1 + r1) (fp16 only), zero agg2 ----------------
__global__ __launch_bounds__(128)
void k_relu1() {
    int i = blockIdx.x * blockDim.x + threadIdx.x;
    if (i >= N_NODES) return;

    const float4* ap = reinterpret_cast<const float4*>(g_agg1 + (size_t)i * R1);
    const float4* rp = reinterpret_cast<const float4*>(g_r1 + (size_t)i * R1);
    float4 a0 = ap[0], a1 = ap[1];
    float4 r0 = rp[0], r1v = rp[1];

    float h[R1];
    h[0] = fmaxf(a0.x + r0.x, 0.f);  h[1] = fmaxf(a0.y + r0.y, 0.f);
    h[2] = fmaxf(a0.z + r0.z, 0.f);  h[3] = fmaxf(a0.w + r0.w, 0.f);
    h[4] = fmaxf(a1.x + r1v.x, 0.f); h[5] = fmaxf(a1.y + r1v.y, 0.f);
    h[6] = fmaxf(a1.z + r1v.z, 0.f); h[7] = fmaxf(a1.w + r1v.w, 0.f);

    reinterpret_cast<uint4*>(g_h1h)[i] = pack_half8(h);

    float4 z = make_float4(0.f, 0.f, 0.f, 0.f);
    float4* a2 = reinterpret_cast<float4*>(g_agg2 + (size_t)i * R1);
    a2[0] = z; a2[1] = z;
}

// ---------------- K5: conv2 + fc1 + fc2 + sum (thread per node; root from fp16 h1h) ----------------
__global__ __launch_bounds__(128)
void k_node2(const float* __restrict__ Wrel2,
             const float* __restrict__ brel2,
             const float* __restrict__ Wroot2,
             const float* __restrict__ Wfc1,
             const float* __restrict__ bfc1,
             const float* __restrict__ Wfc2,
             const float* __restrict__ bfc2,
             float* __restrict__ out) {
    __shared__ float sWr[R1 * R2];
    __shared__ float sWo[R1 * R2];
    __shared__ float sb2[R2];
    __shared__ float sF1[R2 * N1];
    __shared__ float sb3[N1];
    __shared__ float sF2[N1];
    __shared__ float sbf2;
    __shared__ float sred[4];

    int t = threadIdx.x;
    for (int j = t; j < R1 * R2; j += blockDim.x) { sWr[j] = Wrel2[j]; sWo[j] = Wroot2[j]; }
    for (int j = t; j < R2 * N1; j += blockDim.x) sF1[j] = Wfc1[j];
    if (t < R2) sb2[t] = brel2[t];
    if (t < N1) { sb3[t] = bfc1[t]; sF2[t] = Wfc2[t]; }
    if (t == 0) sbf2 = bfc2[0];
    __syncthreads();

    int i = blockIdx.x * blockDim.x + t;
    float o = 0.f;
    if (i < N_NODES) {
        const float4* ap = reinterpret_cast<const float4*>(g_agg2 + (size_t)i * R1);
        float4 u = ap[0], v = ap[1];
        float a[R1] = {u.x, u.y, u.z, u.w, v.x, v.y, v.z, v.w};

        float hr[R1];
        unpack_half8(hr, reinterpret_cast<const uint4*>(g_h1h)[i]);

        float h2[R2];
#pragma unroll
        for (int k = 0; k < R2; k++) h2[k] = sb2[k];
#pragma unroll
        for (int j = 0; j < R1; j++) {
            float aj = a[j], hj = hr[j];
#pragma unroll
            for (int k = 0; k < R2; k++)
                h2[k] += aj * sWr[j * R2 + k] + hj * sWo[j * R2 + k];
        }
#pragma unroll
        for (int k = 0; k < R2; k++) h2[k] = fmaxf(h2[k], 0.f);

        o = sbf2;
#pragma unroll
        for (int m = 0; m < N1; m++) {
            float acc = sb3[m];
#pragma unroll
            for (int k = 0; k < R2; k++) acc += h2[k] * sF1[k * N1 + m];
            o += fmaxf(acc, 0.f) * sF2[m];
        }
        out[i] = o;
    }

    float w = o;
#pragma unroll
    for (int off = 16; off > 0; off >>= 1)
        w += __shfl_down_sync(0xffffffffu, w, off);
    if ((t & 31) == 0) sred[t >> 5] = w;
    __syncthreads();
    if (t == 0) {
        float bs = sred[0] + sred[1] + sred[2] + sred[3];
        atomicAdd(&g_sum, (double)bs);
    }
}

// ---------------- K6: subtract mean ----------------
__global__ void k_mean(float* __restrict__ out) {
    int i = blockIdx.x * blockDim.x + threadIdx.x;
    if (i >= N_NODES) return;
    float m = (float)(g_sum / (double)N_NODES);
    out[i] -= m;
}

// ---------------- launch ----------------
extern "C" void kernel_launch(void* const* d_in, const int* in_sizes, int n_in,
                              void* d_out, int out_size) {
    const float* x      = (const float*)d_in[0];
    const int*   ei     = (const int*)d_in[1];
    const float* Wrel1  = (const float*)d_in[2];
    const float* brel1  = (const float*)d_in[3];
    const float* Wroot1 = (const float*)d_in[4];
    const float* Wrel2  = (const float*)d_in[5];
    const float* brel2  = (const float*)d_in[6];
    const float* Wroot2 = (const float*)d_in[7];
    const float* Wfc1   = (const float*)d_in[8];
    const float* bfc1   = (const float*)d_in[9];
    const float* Wfc2   = (const float*)d_in[10];
    const float* bfc2   = (const float*)d_in[11];
    float* out = (float*)d_out;

    const int node_blocks = (N_NODES + 127) / 128;   // 782
    const int push_blocks = N_EDGES / 2 / 256;       // 6250 exactly

    // 4th launch = push2 (the one ncu profiles)
    k_node1<<<node_blocks, 128>>>(x, Wrel1, brel1, Wroot1);                            // 1
    k_push<1><<<push_blocks, 256>>>(ei);                                               // 2
    k_relu1<<<node_blocks, 128>>>();                                                   // 3
    k_push<2><<<push_blocks, 256>>>(ei);                                               // 4
    k_node2<<<node_blocks, 128>>>(Wrel2, brel2, Wroot2, Wfc1, bfc1, Wfc2, bfc2, out);  // 5
    k_mean<<<node_blocks, 128>>>(out);                                                 // 6
}

// round 17
// speedup vs baseline: 1.2868x; 1.2868x over previous
#include <cuda_runtime.h>
#include <cuda_fp16.h>

#define N_NODES 100000
#define N_EDGES 3200000
#define R0 16
#define R1 8
#define R2 16
#define N1 32
#define KSPLIT 8   // accumulation-depth split: 8 fp16 buffers, depth ~4 each

// ---------------- scratch (device globals; no allocation allowed) ----------------
__device__ __align__(16) __half g_y1h[N_NODES * R1];            // x @ W_rel1, fp16 rows
__device__ __align__(16) float  g_r1[N_NODES * R1];             // x @ W_root1 + b_rel1
__device__ __align__(16) __half g_agg1h[KSPLIT * N_NODES * R1]; // L1 split aggregates (12.8MB)
__device__ __align__(16) __half g_h1h[N_NODES * R1];            // layer-1 out, fp16 rows
__device__ __align__(16) __half g_agg2h[KSPLIT * N_NODES * R1]; // L2 split aggregates (12.8MB)
__device__ double g_sum;

// fp16x2 vector reduction: one L2 op adds 8 halves (16B)
__device__ __forceinline__ void red_add_v4f16x2(__half* p, uint4 u) {
    asm volatile("red.global.add.noftz.v4.f16x2 [%0], {%1, %2, %3, %4};"
                 :: "l"(p), "r"(u.x), "r"(u.y), "r"(u.z), "r"(u.w)
                 : "memory");
}

// pack 8 floats -> 8 halves (16B)
__device__ __forceinline__ uint4 pack_half8(const float* v) {
    __half2 h0 = __float22half2_rn(make_float2(v[0], v[1]));
    __half2 h1 = __float22half2_rn(make_float2(v[2], v[3]));
    __half2 h2 = __float22half2_rn(make_float2(v[4], v[5]));
    __half2 h3 = __float22half2_rn(make_float2(v[6], v[7]));
    uint4 u;
    u.x = *reinterpret_cast<unsigned*>(&h0);
    u.y = *reinterpret_cast<unsigned*>(&h1);
    u.z = *reinterpret_cast<unsigned*>(&h2);
    u.w = *reinterpret_cast<unsigned*>(&h3);
    return u;
}

// accumulate a 16B half8 row into fp32 acc[8]
__device__ __forceinline__ void acc_half8(float* acc, uint4 u) {
    __half2 h0 = *reinterpret_cast<__half2*>(&u.x);
    __half2 h1 = *reinterpret_cast<__half2*>(&u.y);
    __half2 h2 = *reinterpret_cast<__half2*>(&u.z);
    __half2 h3 = *reinterpret_cast<__half2*>(&u.w);
    float2 f0 = __half22float2(h0), f1 = __half22float2(h1);
    float2 f2 = __half22float2(h2), f3 = __half22float2(h3);
    acc[0] += f0.x; acc[1] += f0.y; acc[2] += f1.x; acc[3] += f1.y;
    acc[4] += f2.x; acc[5] += f2.y; acc[6] += f3.x; acc[7] += f3.y;
}

// unpack a 16B half8 row into 8 floats
__device__ __forceinline__ void unpack_half8(float* f, uint4 u) {
    __half2 h0 = *reinterpret_cast<__half2*>(&u.x);
    __half2 h1 = *reinterpret_cast<__half2*>(&u.y);
    __half2 h2 = *reinterpret_cast<__half2*>(&u.z);
    __half2 h3 = *reinterpret_cast<__half2*>(&u.w);
    float2 f0 = __half22float2(h0), f1 = __half22float2(h1);
    float2 f2 = __half22float2(h2), f3 = __half22float2(h3);
    f[0] = f0.x; f[1] = f0.y; f[2] = f1.x; f[3] = f1.y;
    f[4] = f2.x; f[5] = f2.y; f[6] = f3.x; f[7] = f3.y;
}

// ---------------- K1: pre-transform + zero L1 split buffers + zero sum ----------------
__global__ __launch_bounds__(128)
void k_node1(const float* __restrict__ x,
             const float* __restrict__ Wrel,
             const float* __restrict__ brel,
             const float* __restrict__ Wroot) {
    __shared__ float sWr[R0 * R1];
    __shared__ float sWo[R0 * R1];
    __shared__ float sb[R1];
    int t = threadIdx.x;
    if (t < R0 * R1) { sWr[t] = Wrel[t]; sWo[t] = Wroot[t]; }
    if (t < R1) sb[t] = brel[t];
    __syncthreads();

    int i = blockIdx.x * blockDim.x + t;
    if (i == 0) g_sum = 0.0;
    if (i >= N_NODES) return;

    float xr[R0];
    const float4* xp = reinterpret_cast<const float4*>(x + (size_t)i * R0);
#pragma unroll
    for (int q = 0; q < R0 / 4; q++) {
        float4 v = xp[q];
        xr[4 * q + 0] = v.x; xr[4 * q + 1] = v.y;
        xr[4 * q + 2] = v.z; xr[4 * q + 3] = v.w;
    }

    float y[R1], r[R1];
#pragma unroll
    for (int k = 0; k < R1; k++) { y[k] = 0.f; r[k] = sb[k]; }
#pragma unroll
    for (int j = 0; j < R0; j++) {
        float xj = xr[j];
#pragma unroll
        for (int k = 0; k < R1; k++) {
            y[k] += xj * sWr[j * R1 + k];
            r[k] += xj * sWo[j * R1 + k];
        }
    }

    reinterpret_cast<uint4*>(g_y1h)[i] = pack_half8(y);
    float4* rp = reinterpret_cast<float4*>(g_r1 + (size_t)i * R1);
    rp[0] = make_float4(r[0], r[1], r[2], r[3]);
    rp[1] = make_float4(r[4], r[5], r[6], r[7]);

    uint4 z = make_uint4(0u, 0u, 0u, 0u);
    uint4* a1 = reinterpret_cast<uint4*>(g_agg1h);
#pragma unroll
    for (int b = 0; b < KSPLIT; b++)
        a1[(size_t)b * N_NODES + i] = z;
}

// ---------------- K2: layer-1 push — 1 gather + 1 fp16x2 red/edge, split buffers ----------------
__global__ __launch_bounds__(256, 8)
void k_push1(const int* __restrict__ ei) {
    int base = (blockIdx.x * blockDim.x + threadIdx.x) * 2;
    // grid exact: 6250 blocks x 256 threads x 2 edges = 3.2M

    const uint4* rows = reinterpret_cast<const uint4*>(g_y1h);

    int2 s = __ldg(reinterpret_cast<const int2*>(ei + base));
    int2 d = __ldg(reinterpret_cast<const int2*>(ei + N_EDGES + base));

    uint4 r0 = __ldg(rows + s.x);
    uint4 r1 = __ldg(rows + s.y);

    int b0 = base & (KSPLIT - 1);
    int b1 = (base + 1) & (KSPLIT - 1);
    red_add_v4f16x2(g_agg1h + ((size_t)b0 * N_NODES + d.x) * R1, r0);
    red_add_v4f16x2(g_agg1h + ((size_t)b1 * N_NODES + d.y) * R1, r1);
}

// ---------------- K3: combine L1 partials (fp32) + relu; zero L2 buffers ----------------
__global__ __launch_bounds__(128)
void k_relu1() {
    int i = blockIdx.x * blockDim.x + threadIdx.x;
    if (i >= N_NODES) return;

    const uint4* a1 = reinterpret_cast<const uint4*>(g_agg1h);
    float a[R1] = {0.f, 0.f, 0.f, 0.f, 0.f, 0.f, 0.f, 0.f};
#pragma unroll
    for (int b = 0; b < KSPLIT; b++)
        acc_half8(a, __ldg(a1 + (size_t)b * N_NODES + i));

    const float4* rp = reinterpret_cast<const float4*>(g_r1 + (size_t)i * R1);
    float4 r0 = rp[0], r1v = rp[1];

    float h[R1];
    h[0] = fmaxf(a[0] + r0.x, 0.f);  h[1] = fmaxf(a[1] + r0.y, 0.f);
    h[2] = fmaxf(a[2] + r0.z, 0.f);  h[3] = fmaxf(a[3] + r0.w, 0.f);
    h[4] = fmaxf(a[4] + r1v.x, 0.f); h[5] = fmaxf(a[5] + r1v.y, 0.f);
    h[6] = fmaxf(a[6] + r1v.z, 0.f); h[7] = fmaxf(a[7] + r1v.w, 0.f);

    reinterpret_cast<uint4*>(g_h1h)[i] = pack_half8(h);

    uint4 z = make_uint4(0u, 0u, 0u, 0u);
    uint4* a2 = reinterpret_cast<uint4*>(g_agg2h);
#pragma unroll
    for (int b = 0; b < KSPLIT; b++)
        a2[(size_t)b * N_NODES + i] = z;
}

// ---------------- K4: layer-2 push — 1 gather + 1 fp16x2 red/edge, split buffers ----------------
__global__ __launch_bounds__(256, 8)
void k_push2(const int* __restrict__ ei) {
    int base = (blockIdx.x * blockDim.x + threadIdx.x) * 2;

    const uint4* rows = reinterpret_cast<const uint4*>(g_h1h);

    int2 s = __ldg(reinterpret_cast<const int2*>(ei + base));
    int2 d = __ldg(reinterpret_cast<const int2*>(ei + N_EDGES + base));

    uint4 r0 = __ldg(rows + s.x);
    uint4 r1 = __ldg(rows + s.y);

    int b0 = base & (KSPLIT - 1);
    int b1 = (base + 1) & (KSPLIT - 1);
    red_add_v4f16x2(g_agg2h + ((size_t)b0 * N_NODES + d.x) * R1, r0);
    red_add_v4f16x2(g_agg2h + ((size_t)b1 * N_NODES + d.y) * R1, r1);
}

// ---------------- K5: combine L2 partials + conv2 + fc1 + fc2 + sum ----------------
__global__ __launch_bounds__(128)
void k_node2(const float* __restrict__ Wrel2,
             const float* __restrict__ brel2,
             const float* __restrict__ Wroot2,
             const float* __restrict__ Wfc1,
             const float* __restrict__ bfc1,
             const float* __restrict__ Wfc2,
             const float* __restrict__ bfc2,
             float* __restrict__ out) {
    __shared__ float sWr[R1 * R2];
    __shared__ float sWo[R1 * R2];
    __shared__ float sb2[R2];
    __shared__ float sF1[R2 * N1];
    __shared__ float sb3[N1];
    __shared__ float sF2[N1];
    __shared__ float sbf2;
    __shared__ float sred[4];

    int t = threadIdx.x;
    for (int j = t; j < R1 * R2; j += blockDim.x) { sWr[j] = Wrel2[j]; sWo[j] = Wroot2[j]; }
    for (int j = t; j < R2 * N1; j += blockDim.x) sF1[j] = Wfc1[j];
    if (t < R2) sb2[t] = brel2[t];
    if (t < N1) { sb3[t] = bfc1[t]; sF2[t] = Wfc2[t]; }
    if (t == 0) sbf2 = bfc2[0];
    __syncthreads();

    int i = blockIdx.x * blockDim.x + t;
    float o = 0.f;
    if (i < N_NODES) {
        const uint4* a2 = reinterpret_cast<const uint4*>(g_agg2h);
        float a[R1] = {0.f, 0.f, 0.f, 0.f, 0.f, 0.f, 0.f, 0.f};
#pragma unroll
        for (int b = 0; b < KSPLIT; b++)
            acc_half8(a, __ldg(a2 + (size_t)b * N_NODES + i));

        float hr[R1];
        unpack_half8(hr, reinterpret_cast<const uint4*>(g_h1h)[i]);

        float h2[R2];
#pragma unroll
        for (int k = 0; k < R2; k++) h2[k] = sb2[k];
#pragma unroll
        for (int j = 0; j < R1; j++) {
            float aj = a[j], hj = hr[j];
#pragma unroll
            for (int k = 0; k < R2; k++)
                h2[k] += aj * sWr[j * R2 + k] + hj * sWo[j * R2 + k];
        }
#pragma unroll
        for (int k = 0; k < R2; k++) h2[k] = fmaxf(h2[k], 0.f);

        o = sbf2;
#pragma unroll
        for (int m = 0; m < N1; m++) {
            float acc = sb3[m];
#pragma unroll
            for (int k = 0; k < R2; k++) acc += h2[k] * sF1[k * N1 + m];
            o += fmaxf(acc, 0.f) * sF2[m];
        }
        out[i] = o;
    }

    float w = o;
#pragma unroll
    for (int off = 16; off > 0; off >>= 1)
        w += __shfl_down_sync(0xffffffffu, w, off);
    if ((t & 31) == 0) sred[t >> 5] = w;
    __syncthreads();
    if (t == 0) {
        float bs = sred[0] + sred[1] + sred[2] + sred[3];
        atomicAdd(&g_sum, (double)bs);
    }
}

// ---------------- K6: subtract mean ----------------
__global__ void k_mean(float* __restrict__ out) {
    int i = blockIdx.x * blockDim.x + threadIdx.x;
    if (i >= N_NODES) return;
    float m = (float)(g_sum / (double)N_NODES);
    out[i] -= m;
}

// ---------------- launch ----------------
extern "C" void kernel_launch(void* const* d_in, const int* in_sizes, int n_in,
                              void* d_out, int out_size) {
    const float* x      = (const float*)d_in[0];
    const int*   ei     = (const int*)d_in[1];
    const float* Wrel1  = (const float*)d_in[2];
    const float* brel1  = (const float*)d_in[3];
    const float* Wroot1 = (const float*)d_in[4];
    const float* Wrel2  = (const float*)d_in[5];
    const float* brel2  = (const float*)d_in[6];
    const float* Wroot2 = (const float*)d_in[7];
    const float* Wfc1   = (const float*)d_in[8];
    const float* bfc1   = (const float*)d_in[9];
    const float* Wfc2   = (const float*)d_in[10];
    const float* bfc2   = (const float*)d_in[11];
    float* out = (float*)d_out;

    const int node_blocks = (N_NODES + 127) / 128;   // 782
    const int push_blocks = N_EDGES / 2 / 256;       // 6250 exactly

    // 4th launch = push2 (ncu's pick)
    k_node1<<<node_blocks, 128>>>(x, Wrel1, brel1, Wroot1);                            // 1
    k_push1<<<push_blocks, 256>>>(ei);                                                 // 2
    k_relu1<<<node_blocks, 128>>>();                                                   // 3
    k_push2<<<push_blocks, 256>>>(ei);                                                 // 4
    k_node2<<<node_blocks, 128>>>(Wrel2, brel2, Wroot2, Wfc1, bfc1, Wfc2, bfc2, out);  // 5
    k_mean<<<node_blocks, 128>>>(out);                                                 // 6
}